// round 12
// baseline (speedup 1.0000x reference)
#include <cuda_runtime.h>
#include <cuda_bf16.h>
#include <math.h>
#include <stdint.h>

// ============================ problem dims =================================
#define M_ROWS 16384
#define K_DIM  4096
#define N_DIM  4096

// ============================ GEMM tiling ==================================
#define BM 128
#define BN 128
#define BK 32                       // bf16 per k-chunk -> 64B rows in smem
#define KIT (K_DIM / BK)            // 128 k-iterations
#define NSPLIT 2
#define NSTAGES 4

#define TILE_BYTES (128 * 64)       // 8 KB: 128 rows x 32 bf16
#define STAGE_BYTES (3 * TILE_BYTES)        // 2 A-split tiles + 1 B tile = 24 KB
#define SMEM_TILES_OFF 1024
#define DYN_SMEM (SMEM_TILES_OFF + NSTAGES * STAGE_BYTES)   // ~97 KB -> 2 CTAs/SM

// Marginal threshold: |h_tc| < DELTA -> recompute with sequential fp32.
// sigma(|h_tc - h_seq|) ~ 3e-4 (fp32 ordering + 2-split residual); 0.006 = 20 sigma.
#define DELTA 0.006f
#define MAXW  (4u * 1024u * 1024u)

// ============================ device scratch ===============================
__device__ float g_s[M_ROWS];
__device__ unsigned int g_cnt;
__device__ unsigned int g_wl[MAXW];   // packed: sign<<31 | m*4096 + n
__device__ __nv_bfloat16 g_X0[(size_t)M_ROWS * K_DIM];
__device__ __nv_bfloat16 g_X1[(size_t)M_ROWS * K_DIM];
__device__ __nv_bfloat16 g_Wb[(size_t)N_DIM * K_DIM];     // sign(W1) as bf16 +/-1

// ============================ PTX helpers ==================================
__device__ __forceinline__ uint32_t smem_u32(const void* p) {
    uint32_t a;
    asm("{ .reg .u64 t; cvta.to.shared.u64 t, %1; cvt.u32.u64 %0, t; }"
        : "=r"(a) : "l"(p));
    return a;
}

#define CP_ASYNC16(dst, src) \
    asm volatile("cp.async.cg.shared.global [%0], [%1], 16;" \
                 :: "r"(dst), "l"(src) : "memory")
#define CP_COMMIT() asm volatile("cp.async.commit_group;" ::: "memory")
#define CP_WAIT2()  asm volatile("cp.async.wait_group 2;" ::: "memory")

__device__ __forceinline__ void ldm_x4(uint32_t* r, uint32_t addr) {
    asm volatile("ldmatrix.sync.aligned.m8n8.x4.shared.b16 {%0,%1,%2,%3}, [%4];"
                 : "=r"(r[0]), "=r"(r[1]), "=r"(r[2]), "=r"(r[3]) : "r"(addr));
}

__device__ __forceinline__ void mma_bf16(float* c, const uint32_t* a,
                                         const uint32_t* b) {
    asm volatile(
        "mma.sync.aligned.m16n8k16.row.col.f32.bf16.bf16.f32 "
        "{%0,%1,%2,%3}, {%4,%5,%6,%7}, {%8,%9}, {%0,%1,%2,%3};"
        : "+f"(c[0]), "+f"(c[1]), "+f"(c[2]), "+f"(c[3])
        : "r"(a[0]), "r"(a[1]), "r"(a[2]), "r"(a[3]), "r"(b[0]), "r"(b[1]));
}

// smem tile addressing: 128 rows x 64B, 4x 16B chunks/row, swizzled.
__device__ __forceinline__ uint32_t swz(uint32_t base, int row, int chunk) {
    return base + row * 64 + ((chunk ^ ((row >> 1) & 3)) << 4);
}

// ============================ fused prepass ================================
// One launch covers: X 2-way bf16 split (16M float4 items), W1 binarize
// (4M float4 items), g_s/g_cnt zeroing (low ids). All memory-bound; fusing
// overlaps them and drops two kernel launches.
#define X_ITEMS  ((M_ROWS * (size_t)K_DIM) / 4)          // 16M
#define W_ITEMS  ((N_DIM * (size_t)K_DIM) / 4)           // 4M
#define PRE_ITEMS (X_ITEMS + W_ITEMS)

__global__ void prepass_kernel(const float* __restrict__ X,
                               const float* __restrict__ W1) {
    size_t id = (size_t)blockIdx.x * blockDim.x + threadIdx.x;
    if (id < M_ROWS) g_s[id] = 0.0f;
    if (id == 0) g_cnt = 0u;
    if (id >= PRE_ITEMS) return;

    if (id < X_ITEMS) {
        size_t i = id * 4;
        float4 v = *reinterpret_cast<const float4*>(X + i);
        float f[4] = {v.x, v.y, v.z, v.w};
        ushort4 o0, o1;
        unsigned short* p0 = &o0.x;
        unsigned short* p1 = &o1.x;
#pragma unroll
        for (int j = 0; j < 4; ++j) {
            float x = f[j];
            __nv_bfloat16 b0 = __float2bfloat16(x);
            float r1 = x - __bfloat162float(b0);
            __nv_bfloat16 b1 = __float2bfloat16(r1);
            p0[j] = __bfloat16_as_ushort(b0);
            p1[j] = __bfloat16_as_ushort(b1);
        }
        *reinterpret_cast<ushort4*>(&g_X0[i]) = o0;
        *reinterpret_cast<ushort4*>(&g_X1[i]) = o1;
    } else {
        size_t i = (id - X_ITEMS) * 4;
        float4 v = *reinterpret_cast<const float4*>(W1 + i);
        const unsigned short P = 0x3F80, N = 0xBF80;   // bf16 +1 / -1
        ushort4 o;
        o.x = (v.x >= 0.f) ? P : N;
        o.y = (v.y >= 0.f) ? P : N;
        o.z = (v.z >= 0.f) ? P : N;
        o.w = (v.w >= 0.f) ? P : N;
        *reinterpret_cast<ushort4*>(&g_Wb[i]) = o;
    }
}

// ============================ main GEMM (tensor) ===========================
// 8 warps (4m x 2n), warp tile 32x64, mma.sync m16n8k16 bf16, 4-stage
// cp.async pipeline, 2 CTAs/SM, single barrier per k-iteration, unroll x4.
__global__ __launch_bounds__(256, 2)
void gemm_mma_kernel(const float* __restrict__ W2) {
    extern __shared__ char dsm[];
    const uint32_t sb = smem_u32(dsm);
    float* w2s = reinterpret_cast<float*>(dsm);          // [128]
    const uint32_t tiles = sb + SMEM_TILES_OFF;

    const int tid  = threadIdx.x;
    const int wid  = tid >> 5;
    const int lane = tid & 31;
    const int WM   = (wid >> 1) * 32;
    const int WN   = (wid & 1) * 64;

    // Supertiled CTA order: 8 m-blocks x 32 n-blocks per supertile.
    const int bid = blockIdx.x;
    const int sid = bid >> 8;
    const int rem = bid & 255;
    const int bm  = (sid * 8 + (rem & 7)) * BM;
    const int bn  = (rem >> 3) * BN;

    if (tid < BN) w2s[tid] = (W2[bn + tid] >= 0.f) ? 1.f : -1.f;

    const __nv_bfloat16* abase[NSPLIT] = {
        g_X0 + (size_t)bm * K_DIM,
        g_X1 + (size_t)bm * K_DIM };
    const __nv_bfloat16* bbase = g_Wb + (size_t)bn * K_DIM;

#define LOAD_STAGE(stg, kt) do {                                              \
    const int _k0 = (kt) * BK;                                                \
    const uint32_t _sb0 = tiles + (stg) * STAGE_BYTES;                        \
    _Pragma("unroll")                                                         \
    for (int _t = 0; _t < 3; ++_t) {                                          \
        const __nv_bfloat16* _g = (_t < 2) ? abase[_t] : bbase;               \
        const uint32_t _tb = _sb0 + _t * TILE_BYTES;                          \
        _Pragma("unroll")                                                     \
        for (int _j = 0; _j < 2; ++_j) {                                      \
            int _id  = tid + _j * 256;                                        \
            int _row = _id >> 2;                                              \
            int _c   = _id & 3;                                               \
            CP_ASYNC16(swz(_tb, _row, _c),                                    \
                       _g + (size_t)_row * K_DIM + _k0 + _c * 8);             \
        }                                                                     \
    }                                                                         \
    CP_COMMIT();                                                              \
} while (0)

    LOAD_STAGE(0, 0);
    LOAD_STAGE(1, 1);
    LOAD_STAGE(2, 2);

    float acc[2][8][4];
#pragma unroll
    for (int mi = 0; mi < 2; ++mi)
#pragma unroll
        for (int ni = 0; ni < 8; ++ni)
#pragma unroll
            for (int e = 0; e < 4; ++e) acc[mi][ni][e] = 0.f;

    const int arow  = WM + (lane & 7) + ((lane >> 3) & 1) * 8;
    const int achk  = lane >> 4;
    const int brow0 = WN + (lane & 7) + ((lane >> 4) & 1) * 8;
    const int bchk  = (lane >> 3) & 1;

    // One k-iteration body, single leading barrier (WAR analysis: the load
    // issued at iteration it writes stage (it+3)&3 = stage computed at it-1,
    // which every warp has finished before passing this iteration's barrier).
#define K_ITER(it) do {                                                       \
    CP_WAIT2();                                                               \
    __syncthreads();                                                          \
    if ((it) + 3 < KIT) LOAD_STAGE(((it) + 3) & 3, (it) + 3);                 \
    else                CP_COMMIT();                                          \
    const uint32_t s0 = tiles + ((it) & 3) * STAGE_BYTES;                     \
    const uint32_t bt = s0 + 2 * TILE_BYTES;                                  \
    _Pragma("unroll")                                                         \
    for (int ks = 0; ks < 2; ++ks) {                                          \
        uint32_t br[16];                                                      \
        _Pragma("unroll")                                                     \
        for (int gi = 0; gi < 4; ++gi)                                        \
            ldm_x4(&br[gi * 4], swz(bt, brow0 + gi * 16, 2 * ks + bchk));     \
        _Pragma("unroll")                                                     \
        for (int p = 0; p < NSPLIT; ++p) {                                    \
            const uint32_t at = s0 + p * TILE_BYTES;                          \
            uint32_t ar[8];                                                   \
            ldm_x4(&ar[0], swz(at, arow,      2 * ks + achk));                \
            ldm_x4(&ar[4], swz(at, arow + 16, 2 * ks + achk));                \
            _Pragma("unroll")                                                 \
            for (int mi = 0; mi < 2; ++mi)                                    \
                _Pragma("unroll")                                             \
                for (int ni = 0; ni < 8; ++ni)                                \
                    mma_bf16(acc[mi][ni], &ar[mi * 4],                        \
                             &br[(ni >> 1) * 4 + (ni & 1) * 2]);              \
        }                                                                     \
    }                                                                         \
} while (0)

    // Unroll x4 over k-iterations (KIT % 4 == 0).
    for (int it = 0; it < KIT; it += 4) {
        K_ITER(it);
        K_ITER(it + 1);
        K_ITER(it + 2);
        K_ITER(it + 3);
    }

    // --------------------------- epilogue ----------------------------------
    // acc[mi][ni][e]: m = WM + mi*16 + (lane>>2) + (e>=2)*8
    //                 n = WN + ni*8 + (lane&3)*2 + (e&1)
    float rs[2][2] = {{0.f, 0.f}, {0.f, 0.f}};
#pragma unroll
    for (int mi = 0; mi < 2; ++mi)
#pragma unroll
        for (int ni = 0; ni < 8; ++ni)
#pragma unroll
            for (int e = 0; e < 4; ++e) {
                float h = acc[mi][ni][e];
                int nl = WN + ni * 8 + (lane & 3) * 2 + (e & 1);
                float w = w2s[nl];
                bool pos = (h >= 0.f);
                rs[mi][e >> 1] += pos ? w : -w;
                if (fabsf(h) < DELTA) {   // marginal: queue fp32 recheck
                    int m = bm + WM + mi * 16 + (lane >> 2) + (e >> 1) * 8;
                    unsigned idx = atomicAdd(&g_cnt, 1u);
                    if (idx < MAXW)
                        g_wl[idx] = (unsigned)(m * 4096 + (bn + nl)) |
                                    (pos ? 0x80000000u : 0u);
                }
            }

#pragma unroll
    for (int mi = 0; mi < 2; ++mi)
#pragma unroll
        for (int eh = 0; eh < 2; ++eh) {
            rs[mi][eh] += __shfl_xor_sync(0xffffffffu, rs[mi][eh], 1);
            rs[mi][eh] += __shfl_xor_sync(0xffffffffu, rs[mi][eh], 2);
        }

    if ((lane & 3) == 0) {
#pragma unroll
        for (int mi = 0; mi < 2; ++mi)
#pragma unroll
            for (int eh = 0; eh < 2; ++eh) {
                int m = bm + WM + mi * 16 + (lane >> 2) + eh * 8;
                atomicAdd(&g_s[m], rs[mi][eh]);
            }
    }
#undef K_ITER
#undef LOAD_STAGE
}

// ===================== correction: sequential fp32 recheck =================
// Recompute marginal h with a strictly k-ascending single-accumulator fp32
// FMA chain (round-1 arithmetic, matches the reference rounding class).
// Apply +/-2*w2 delta on sign flip; deltas additive -> order-independent.
__global__ void correction_kernel(const float* __restrict__ X,
                                  const float* __restrict__ W1,
                                  const float* __restrict__ W2) {
    unsigned cnt = g_cnt;
    if (cnt > MAXW) cnt = MAXW;
    for (unsigned i = blockIdx.x * blockDim.x + threadIdx.x; i < cnt;
         i += gridDim.x * blockDim.x) {
        unsigned e = g_wl[i];
        bool sign_tc = (e >> 31) != 0u;
        unsigned v = e & 0x7FFFFFFFu;
        int m = (int)(v >> 12);
        int n = (int)(v & 4095u);
        const float* xr = X  + (size_t)m * K_DIM;
        const float* wr = W1 + (size_t)n * K_DIM;
        float acc = 0.f;
        for (int k = 0; k < K_DIM; k += 4) {
            float4 xv = *reinterpret_cast<const float4*>(xr + k);
            float4 wv = *reinterpret_cast<const float4*>(wr + k);
            acc = fmaf(xv.x, (wv.x >= 0.f) ? 1.f : -1.f, acc);
            acc = fmaf(xv.y, (wv.y >= 0.f) ? 1.f : -1.f, acc);
            acc = fmaf(xv.z, (wv.z >= 0.f) ? 1.f : -1.f, acc);
            acc = fmaf(xv.w, (wv.w >= 0.f) ? 1.f : -1.f, acc);
        }
        bool sign_seq = (acc >= 0.f);
        if (sign_seq != sign_tc) {
            float w = (W2[n] >= 0.f) ? 1.f : -1.f;
            atomicAdd(&g_s[m], sign_seq ? 2.f * w : -2.f * w);
        }
    }
}

// ============================ finalize =====================================
__global__ void finalize_kernel(float* __restrict__ out, int out_size) {
    int b = blockIdx.x * blockDim.x + threadIdx.x;
    if (b >= M_ROWS) return;
    float s = g_s[b];
    float o = 1.0f / (1.0f + expf(-s));
    if (b < out_size) out[b] = o;
    int yi = M_ROWS + b;
    if (yi < out_size) out[yi] = (s >= 0.0f) ? 1.0f : 0.0f;
}

// ============================ launcher =====================================
extern "C" void kernel_launch(void* const* d_in, const int* in_sizes, int n_in,
                              void* d_out, int out_size) {
    const float* X  = (const float*)d_in[0];   // [16384, 4096]
    const float* W1 = (const float*)d_in[1];   // [4096, 4096]
    const float* W2 = (const float*)d_in[2];   // [4096]
    float* out = (float*)d_out;

    cudaFuncSetAttribute(gemm_mma_kernel,
                         cudaFuncAttributeMaxDynamicSharedMemorySize, DYN_SMEM);

    prepass_kernel<<<(unsigned)((PRE_ITEMS + 255) / 256), 256>>>(X, W1);

    gemm_mma_kernel<<<(M_ROWS / BM) * (N_DIM / BN), 256, DYN_SMEM>>>(W2);

    correction_kernel<<<256, 256>>>(X, W1, W2);

    finalize_kernel<<<(M_ROWS + 255) / 256, 256>>>(out, out_size);
}

// round 13
// speedup vs baseline: 1.1224x; 1.1224x over previous
#include <cuda_runtime.h>
#include <cuda_bf16.h>
#include <math.h>
#include <stdint.h>

// ============================ problem dims =================================
#define M_ROWS 16384
#define K_DIM  4096
#define N_DIM  4096

// ============================ GEMM tiling ==================================
#define BM 128
#define BN 128
#define BK 32                       // bf16 per k-chunk -> 64B rows in smem
#define KIT (K_DIM / BK)            // 128 k-iterations
#define NSPLIT 2
#define NSTAGES 4

#define TILE_BYTES (128 * 64)       // 8 KB: 128 rows x 32 bf16
#define STAGE_BYTES (3 * TILE_BYTES)        // 2 A-split tiles + 1 B tile = 24 KB
#define SMEM_TILES_OFF 1024
#define DYN_SMEM (SMEM_TILES_OFF + NSTAGES * STAGE_BYTES)   // ~97 KB -> 2 CTAs/SM

// Marginal threshold: |h_tc| < DELTA -> recompute with sequential fp32.
// sigma(|h_tc - h_seq|) ~ 3e-4 (fp32 ordering + 2-split residual); 0.006 = 20 sigma.
#define DELTA 0.006f
#define MAXW  (4u * 1024u * 1024u)

// ============================ device scratch ===============================
__device__ float g_s[M_ROWS];
__device__ unsigned int g_cnt;
__device__ unsigned int g_wl[MAXW];   // packed: sign<<31 | m*4096 + n
__device__ __nv_bfloat16 g_X0[(size_t)M_ROWS * K_DIM];
__device__ __nv_bfloat16 g_X1[(size_t)M_ROWS * K_DIM];
__device__ __nv_bfloat16 g_Wb[(size_t)N_DIM * K_DIM];     // sign(W1) as bf16 +/-1

// ============================ PTX helpers ==================================
__device__ __forceinline__ uint32_t smem_u32(const void* p) {
    uint32_t a;
    asm("{ .reg .u64 t; cvta.to.shared.u64 t, %1; cvt.u32.u64 %0, t; }"
        : "=r"(a) : "l"(p));
    return a;
}

#define CP_ASYNC16(dst, src) \
    asm volatile("cp.async.cg.shared.global [%0], [%1], 16;" \
                 :: "r"(dst), "l"(src) : "memory")
#define CP_COMMIT() asm volatile("cp.async.commit_group;" ::: "memory")
#define CP_WAIT2()  asm volatile("cp.async.wait_group 2;" ::: "memory")

__device__ __forceinline__ void ldm_x4(uint32_t* r, uint32_t addr) {
    asm volatile("ldmatrix.sync.aligned.m8n8.x4.shared.b16 {%0,%1,%2,%3}, [%4];"
                 : "=r"(r[0]), "=r"(r[1]), "=r"(r[2]), "=r"(r[3]) : "r"(addr));
}

__device__ __forceinline__ void mma_bf16(float* c, const uint32_t* a,
                                         const uint32_t* b) {
    asm volatile(
        "mma.sync.aligned.m16n8k16.row.col.f32.bf16.bf16.f32 "
        "{%0,%1,%2,%3}, {%4,%5,%6,%7}, {%8,%9}, {%0,%1,%2,%3};"
        : "+f"(c[0]), "+f"(c[1]), "+f"(c[2]), "+f"(c[3])
        : "r"(a[0]), "r"(a[1]), "r"(a[2]), "r"(a[3]), "r"(b[0]), "r"(b[1]));
}

// smem tile addressing: 128 rows x 64B, 4x 16B chunks/row, swizzled.
__device__ __forceinline__ uint32_t swz(uint32_t base, int row, int chunk) {
    return base + row * 64 + ((chunk ^ ((row >> 1) & 3)) << 4);
}

// ============================ prepass kernels ==============================
__global__ void zero_s_kernel() {
    int i = blockIdx.x * blockDim.x + threadIdx.x;
    if (i < M_ROWS) g_s[i] = 0.0f;
    if (i == 0) g_cnt = 0u;
}

__global__ void binarize_w1_kernel(const float* __restrict__ W1) {
    size_t i = ((size_t)blockIdx.x * blockDim.x + threadIdx.x) * 4;
    float4 v = *reinterpret_cast<const float4*>(W1 + i);
    const unsigned short P = 0x3F80, N = 0xBF80;   // bf16 +1 / -1
    ushort4 o;
    o.x = (v.x >= 0.f) ? P : N;
    o.y = (v.y >= 0.f) ? P : N;
    o.z = (v.z >= 0.f) ? P : N;
    o.w = (v.w >= 0.f) ? P : N;
    *reinterpret_cast<ushort4*>(&g_Wb[i]) = o;
}

// 2-way bf16 split: x ~ b0+b1, residual <= 2^-17 |x|; products with +/-1 are
// exact, so |h_tc - h_seq| sigma ~3e-4 << DELTA; correction fixes all signs.
__global__ void split_x_kernel(const float* __restrict__ X) {
    size_t i = ((size_t)blockIdx.x * blockDim.x + threadIdx.x) * 4;
    float4 v = *reinterpret_cast<const float4*>(X + i);
    float f[4] = {v.x, v.y, v.z, v.w};
    ushort4 o0, o1;
    unsigned short* p0 = &o0.x;
    unsigned short* p1 = &o1.x;
#pragma unroll
    for (int j = 0; j < 4; ++j) {
        float x = f[j];
        __nv_bfloat16 b0 = __float2bfloat16(x);
        float r1 = x - __bfloat162float(b0);
        __nv_bfloat16 b1 = __float2bfloat16(r1);
        p0[j] = __bfloat16_as_ushort(b0);
        p1[j] = __bfloat16_as_ushort(b1);
    }
    *reinterpret_cast<ushort4*>(&g_X0[i]) = o0;
    *reinterpret_cast<ushort4*>(&g_X1[i]) = o1;
}

// ============================ main GEMM (tensor) ===========================
// 8 warps (4m x 2n), warp tile 32x64, mma.sync m16n8k16 bf16, 4-stage
// cp.async pipeline, 2 CTAs/SM, single barrier per k-iteration, unroll x4.
// All asm are volatile (source order = SASS order), so fragments are loaded
// in one front-loaded group per ks-half and the cp.async issue block is
// placed between the ks=0 loads and MMAs to hide LDSM latency.
__global__ __launch_bounds__(256, 2)
void gemm_mma_kernel(const float* __restrict__ W2) {
    extern __shared__ char dsm[];
    const uint32_t sb = smem_u32(dsm);
    float* w2s = reinterpret_cast<float*>(dsm);          // [128]
    const uint32_t tiles = sb + SMEM_TILES_OFF;

    const int tid  = threadIdx.x;
    const int wid  = tid >> 5;
    const int lane = tid & 31;
    const int WM   = (wid >> 1) * 32;
    const int WN   = (wid & 1) * 64;

    // Supertiled CTA order: 8 m-blocks x 32 n-blocks per supertile.
    const int bid = blockIdx.x;
    const int sid = bid >> 8;
    const int rem = bid & 255;
    const int bm  = (sid * 8 + (rem & 7)) * BM;
    const int bn  = (rem >> 3) * BN;

    if (tid < BN) w2s[tid] = (W2[bn + tid] >= 0.f) ? 1.f : -1.f;

    const __nv_bfloat16* abase[NSPLIT] = {
        g_X0 + (size_t)bm * K_DIM,
        g_X1 + (size_t)bm * K_DIM };
    const __nv_bfloat16* bbase = g_Wb + (size_t)bn * K_DIM;

#define LOAD_STAGE(stg, kt) do {                                              \
    const int _k0 = (kt) * BK;                                                \
    const uint32_t _sb0 = tiles + (stg) * STAGE_BYTES;                        \
    _Pragma("unroll")                                                         \
    for (int _t = 0; _t < 3; ++_t) {                                          \
        const __nv_bfloat16* _g = (_t < 2) ? abase[_t] : bbase;               \
        const uint32_t _tb = _sb0 + _t * TILE_BYTES;                          \
        _Pragma("unroll")                                                     \
        for (int _j = 0; _j < 2; ++_j) {                                      \
            int _id  = tid + _j * 256;                                        \
            int _row = _id >> 2;                                              \
            int _c   = _id & 3;                                               \
            CP_ASYNC16(swz(_tb, _row, _c),                                    \
                       _g + (size_t)_row * K_DIM + _k0 + _c * 8);             \
        }                                                                     \
    }                                                                         \
    CP_COMMIT();                                                              \
} while (0)

    LOAD_STAGE(0, 0);
    LOAD_STAGE(1, 1);
    LOAD_STAGE(2, 2);

    float acc[2][8][4];
#pragma unroll
    for (int mi = 0; mi < 2; ++mi)
#pragma unroll
        for (int ni = 0; ni < 8; ++ni)
#pragma unroll
            for (int e = 0; e < 4; ++e) acc[mi][ni][e] = 0.f;

    const int arow  = WM + (lane & 7) + ((lane >> 3) & 1) * 8;
    const int achk  = lane >> 4;
    const int brow0 = WN + (lane & 7) + ((lane >> 4) & 1) * 8;
    const int bchk  = (lane >> 3) & 1;

    // Fragment loads for one ks-half: 4 B + 2+2 A (both planes) = 8 ldmatrix.
#define LOAD_FRAGS(s0, bt, ks, br, ar)  do {                                  \
    _Pragma("unroll")                                                         \
    for (int gi = 0; gi < 4; ++gi)                                            \
        ldm_x4(&(br)[gi * 4], swz((bt), brow0 + gi * 16, 2 * (ks) + bchk));   \
    _Pragma("unroll")                                                         \
    for (int p = 0; p < NSPLIT; ++p) {                                        \
        const uint32_t _at = (s0) + p * TILE_BYTES;                           \
        ldm_x4(&(ar)[p * 8],     swz(_at, arow,      2 * (ks) + achk));       \
        ldm_x4(&(ar)[p * 8 + 4], swz(_at, arow + 16, 2 * (ks) + achk));       \
    }                                                                         \
} while (0)

    // All 32 MMAs for one ks-half (both planes).
#define DO_MMAS(br, ar) do {                                                  \
    _Pragma("unroll")                                                         \
    for (int p = 0; p < NSPLIT; ++p)                                          \
        _Pragma("unroll")                                                     \
        for (int mi = 0; mi < 2; ++mi)                                        \
            _Pragma("unroll")                                                 \
            for (int ni = 0; ni < 8; ++ni)                                    \
                mma_bf16(acc[mi][ni], &(ar)[p * 8 + mi * 4],                  \
                         &(br)[(ni >> 1) * 4 + (ni & 1) * 2]);                \
} while (0)

    // One k-iteration: barrier, front-loaded ks=0 fragment loads, cp.async
    // block (hides LDSM latency), ks=0 MMAs, ks=1 loads, ks=1 MMAs.
#define K_ITER(it) do {                                                       \
    CP_WAIT2();                                                               \
    __syncthreads();                                                          \
    const uint32_t s0 = tiles + ((it) & 3) * STAGE_BYTES;                     \
    const uint32_t bt = s0 + 2 * TILE_BYTES;                                  \
    uint32_t br[16], ar[16];                                                  \
    LOAD_FRAGS(s0, bt, 0, br, ar);                                            \
    if ((it) + 3 < KIT) LOAD_STAGE(((it) + 3) & 3, (it) + 3);                 \
    else                CP_COMMIT();                                          \
    DO_MMAS(br, ar);                                                          \
    LOAD_FRAGS(s0, bt, 1, br, ar);                                            \
    DO_MMAS(br, ar);                                                          \
} while (0)

    // Unroll x4 over k-iterations (KIT % 4 == 0).
    for (int it = 0; it < KIT; it += 4) {
        K_ITER(it);
        K_ITER(it + 1);
        K_ITER(it + 2);
        K_ITER(it + 3);
    }

    // --------------------------- epilogue ----------------------------------
    // acc[mi][ni][e]: m = WM + mi*16 + (lane>>2) + (e>=2)*8
    //                 n = WN + ni*8 + (lane&3)*2 + (e&1)
    float rs[2][2] = {{0.f, 0.f}, {0.f, 0.f}};
#pragma unroll
    for (int mi = 0; mi < 2; ++mi)
#pragma unroll
        for (int ni = 0; ni < 8; ++ni)
#pragma unroll
            for (int e = 0; e < 4; ++e) {
                float h = acc[mi][ni][e];
                int nl = WN + ni * 8 + (lane & 3) * 2 + (e & 1);
                float w = w2s[nl];
                bool pos = (h >= 0.f);
                rs[mi][e >> 1] += pos ? w : -w;
                if (fabsf(h) < DELTA) {   // marginal: queue fp32 recheck
                    int m = bm + WM + mi * 16 + (lane >> 2) + (e >> 1) * 8;
                    unsigned idx = atomicAdd(&g_cnt, 1u);
                    if (idx < MAXW)
                        g_wl[idx] = (unsigned)(m * 4096 + (bn + nl)) |
                                    (pos ? 0x80000000u : 0u);
                }
            }

#pragma unroll
    for (int mi = 0; mi < 2; ++mi)
#pragma unroll
        for (int eh = 0; eh < 2; ++eh) {
            rs[mi][eh] += __shfl_xor_sync(0xffffffffu, rs[mi][eh], 1);
            rs[mi][eh] += __shfl_xor_sync(0xffffffffu, rs[mi][eh], 2);
        }

    if ((lane & 3) == 0) {
#pragma unroll
        for (int mi = 0; mi < 2; ++mi)
#pragma unroll
            for (int eh = 0; eh < 2; ++eh) {
                int m = bm + WM + mi * 16 + (lane >> 2) + eh * 8;
                atomicAdd(&g_s[m], rs[mi][eh]);
            }
    }
#undef K_ITER
#undef DO_MMAS
#undef LOAD_FRAGS
#undef LOAD_STAGE
}

// ===================== correction: sequential fp32 recheck =================
// Recompute marginal h with a strictly k-ascending single-accumulator fp32
// FMA chain (round-1 arithmetic, matches the reference rounding class).
// Apply +/-2*w2 delta on sign flip; deltas additive -> order-independent.
__global__ void correction_kernel(const float* __restrict__ X,
                                  const float* __restrict__ W1,
                                  const float* __restrict__ W2) {
    unsigned cnt = g_cnt;
    if (cnt > MAXW) cnt = MAXW;
    for (unsigned i = blockIdx.x * blockDim.x + threadIdx.x; i < cnt;
         i += gridDim.x * blockDim.x) {
        unsigned e = g_wl[i];
        bool sign_tc = (e >> 31) != 0u;
        unsigned v = e & 0x7FFFFFFFu;
        int m = (int)(v >> 12);
        int n = (int)(v & 4095u);
        const float* xr = X  + (size_t)m * K_DIM;
        const float* wr = W1 + (size_t)n * K_DIM;
        float acc = 0.f;
        for (int k = 0; k < K_DIM; k += 4) {
            float4 xv = *reinterpret_cast<const float4*>(xr + k);
            float4 wv = *reinterpret_cast<const float4*>(wr + k);
            acc = fmaf(xv.x, (wv.x >= 0.f) ? 1.f : -1.f, acc);
            acc = fmaf(xv.y, (wv.y >= 0.f) ? 1.f : -1.f, acc);
            acc = fmaf(xv.z, (wv.z >= 0.f) ? 1.f : -1.f, acc);
            acc = fmaf(xv.w, (wv.w >= 0.f) ? 1.f : -1.f, acc);
        }
        bool sign_seq = (acc >= 0.f);
        if (sign_seq != sign_tc) {
            float w = (W2[n] >= 0.f) ? 1.f : -1.f;
            atomicAdd(&g_s[m], sign_seq ? 2.f * w : -2.f * w);
        }
    }
}

// ============================ finalize =====================================
__global__ void finalize_kernel(float* __restrict__ out, int out_size) {
    int b = blockIdx.x * blockDim.x + threadIdx.x;
    if (b >= M_ROWS) return;
    float s = g_s[b];
    float o = 1.0f / (1.0f + expf(-s));
    if (b < out_size) out[b] = o;
    int yi = M_ROWS + b;
    if (yi < out_size) out[yi] = (s >= 0.0f) ? 1.0f : 0.0f;
}

// ============================ launcher =====================================
extern "C" void kernel_launch(void* const* d_in, const int* in_sizes, int n_in,
                              void* d_out, int out_size) {
    const float* X  = (const float*)d_in[0];   // [16384, 4096]
    const float* W1 = (const float*)d_in[1];   // [4096, 4096]
    const float* W2 = (const float*)d_in[2];   // [4096]
    float* out = (float*)d_out;

    cudaFuncSetAttribute(gemm_mma_kernel,
                         cudaFuncAttributeMaxDynamicSharedMemorySize, DYN_SMEM);

    binarize_w1_kernel<<<(N_DIM * (size_t)K_DIM) / (4 * 256), 256>>>(W1);
    split_x_kernel<<<(M_ROWS * (size_t)K_DIM) / (4 * 256), 256>>>(X);
    zero_s_kernel<<<(M_ROWS + 255) / 256, 256>>>();

    gemm_mma_kernel<<<(M_ROWS / BM) * (N_DIM / BN), 256, DYN_SMEM>>>(W2);

    correction_kernel<<<1024, 128>>>(X, W1, W2);

    finalize_kernel<<<(M_ROWS + 255) / 256, 256>>>(out, out_size);
}